// round 9
// baseline (speedup 1.0000x reference)
#include <cuda_runtime.h>
#include <cstdint>

#define NF      1024
#define NB      256
#define NL      17
#define BATCHN  16384
#define RPB     4           // rows per CTA (hardcoded in transposed layout)
#define TPB     256

typedef unsigned long long ull;

// ---------- packed f32x2 helpers ----------
__device__ __forceinline__ ull pk2(float lo, float hi) {
    ull r; asm("mov.b64 %0,{%1,%2};" : "=l"(r) : "f"(lo), "f"(hi)); return r;
}
__device__ __forceinline__ void upk2(ull v, float& a, float& b) {
    asm("mov.b64 {%0,%1},%2;" : "=f"(a), "=f"(b) : "l"(v));
}
__device__ __forceinline__ ull fma2_(ull a, ull b, ull c) {
    ull d; asm("fma.rn.f32x2 %0,%1,%2,%3;" : "=l"(d) : "l"(a), "l"(b), "l"(c)); return d;
}
__device__ __forceinline__ ull mul2_(ull a, ull b) {
    ull d; asm("mul.rn.f32x2 %0,%1,%2;" : "=l"(d) : "l"(a), "l"(b)); return d;
}
__device__ __forceinline__ ull add2_(ull a, ull b) {
    ull d; asm("add.rn.f32x2 %0,%1,%2;" : "=l"(d) : "l"(a), "l"(b)); return d;
}
__device__ __forceinline__ float rsq_(float x) {
    float r; asm("rsqrt.approx.f32 %0,%1;" : "=f"(r) : "f"(x)); return r;
}
__device__ __forceinline__ float lg2_(float x) {
    float r; asm("lg2.approx.f32 %0,%1;" : "=f"(r) : "f"(x)); return r;
}

// ---------- device scratch ----------
__device__ ull   g_Epk[NL * 2 * 4 * NB];
__device__ float g_trace[1];

// ---------- prep: expm of each 4x4 block (fp32 scaling & squaring) ----------
__global__ void prep_expm(const float* __restrict__ vs) {
    int m = blockIdx.x * blockDim.x + threadIdx.x;
    if (m >= NL * NB) return;
    const float* src = vs + m * 16;
    float A[16];
#pragma unroll
    for (int i = 0; i < 16; i++) A[i] = src[i];

    float nrm = 0.f;
#pragma unroll
    for (int r = 0; r < 4; r++) {
        float s = fabsf(A[r * 4 + 0]) + fabsf(A[r * 4 + 1]) +
                  fabsf(A[r * 4 + 2]) + fabsf(A[r * 4 + 3]);
        nrm = fmaxf(nrm, s);
    }
    int sc = 0;
    while (nrm > 0.25f && sc < 40) { nrm *= 0.5f; sc++; }
    float f = 1.f;
    for (int i = 0; i < sc; i++) f *= 0.5f;
#pragma unroll
    for (int i = 0; i < 16; i++) A[i] *= f;

    float X[16], T[16];
#pragma unroll
    for (int i = 0; i < 16; i++) { X[i] = A[i]; T[i] = A[i]; }
    X[0] += 1.f; X[5] += 1.f; X[10] += 1.f; X[15] += 1.f;

#pragma unroll 1
    for (int k = 2; k <= 9; k++) {
        float Tn[16];
        float inv = 1.f / (float)k;
#pragma unroll
        for (int r = 0; r < 4; r++)
#pragma unroll
            for (int c = 0; c < 4; c++) {
                float s = T[r * 4 + 0] * A[0 * 4 + c];
                s = fmaf(T[r * 4 + 1], A[1 * 4 + c], s);
                s = fmaf(T[r * 4 + 2], A[2 * 4 + c], s);
                s = fmaf(T[r * 4 + 3], A[3 * 4 + c], s);
                Tn[r * 4 + c] = s * inv;
            }
#pragma unroll
        for (int i = 0; i < 16; i++) { T[i] = Tn[i]; X[i] += T[i]; }
    }
#pragma unroll 1
    for (int q = 0; q < sc; q++) {
        float Xn[16];
#pragma unroll
        for (int r = 0; r < 4; r++)
#pragma unroll
            for (int c = 0; c < 4; c++) {
                float s = X[r * 4 + 0] * X[0 * 4 + c];
                s = fmaf(X[r * 4 + 1], X[1 * 4 + c], s);
                s = fmaf(X[r * 4 + 2], X[2 * 4 + c], s);
                s = fmaf(X[r * 4 + 3], X[3 * 4 + c], s);
                Xn[r * 4 + c] = s;
            }
#pragma unroll
        for (int i = 0; i < 16; i++) X[i] = Xn[i];
    }

    int l = m / NB, n = m % NB;
    float2* Ep = (float2*)g_Epk;
#pragma unroll
    for (int e = 0; e < 4; e++) {
        Ep[((l * 2 + 0) * 4 + e) * NB + n] = make_float2(X[e * 4 + 0], X[e * 4 + 1]);
        Ep[((l * 2 + 1) * 4 + e) * NB + n] = make_float2(X[e * 4 + 2], X[e * 4 + 3]);
    }
}

// ---------- prep: deterministic trace sum ----------
__global__ void prep_trace(const float* __restrict__ vs) {
    __shared__ float red[256];
    int t = threadIdx.x;
    float s = 0.f;
    for (int m = t; m < NL * NB; m += 256) {
        const float* p = vs + m * 16;
        s += p[0] + p[5] + p[10] + p[15];
    }
    red[t] = s;
    __syncthreads();
    for (int o = 128; o > 0; o >>= 1) {
        if (t < o) red[t] += red[t + o];
        __syncthreads();
    }
    if (t == 0) g_trace[0] = red[0];
}

// ---------- main fused flow kernel ----------
// Transposed+swizzled smem layout: element (feature f, row rl) at float offset
//   (f & 3) * 1024 + (f >> 2) * 4 + rl
// -> one float4 chunk per feature holds all RPB=4 rows.
// Read (gather) = 1 LDS.128 per gathered feature; write = 4 conflict-free STS.128.
extern __shared__ float smem[];

// chunk pointer for feature g inside a buffer (as float4*)
#define CHUNK(bufp, g) (((float4*)(bufp)) + (((g) & 3) << 8) + ((g) >> 2))

// bent-identity + 4x4 matmul on one row (component C of G0..G3, row index RL),
// in-place update of G registers, Jacobian factor into accp[RL]
#define ROWBODY(C, RL)                                                          \
    do {                                                                        \
        ull Z01 = pk2(G0.C, G1.C), Z23 = pk2(G2.C, G3.C);                       \
        ull T01 = fma2_(Z01, Z01, ONE2), T23 = fma2_(Z23, Z23, ONE2);           \
        float t0, t1, t2, t3;                                                   \
        upk2(T01, t0, t1); upk2(T23, t2, t3);                                   \
        ull R01 = pk2(rsq_(t0), rsq_(t1)), R23 = pk2(rsq_(t2), rsq_(t3));       \
        ull S01 = mul2_(T01, R01), S23 = mul2_(T23, R23);                       \
        ull U01 = mul2_(Z01, R01), U23 = mul2_(Z23, R23);                       \
        ull D01 = fma2_(HALF2, U01, ONE2), D23 = fma2_(HALF2, U23, ONE2);       \
        ull P = mul2_(D01, D23);                                                \
        float p0, p1; upk2(P, p0, p1);                                          \
        accp[RL] *= (p0 * p1);                                                  \
        ull Zn01 = add2_(fma2_(HALF2, S01, Z01), NHALF2);                       \
        ull Zn23 = add2_(fma2_(HALF2, S23, Z23), NHALF2);                       \
        float z0, z1, z2, z3;                                                   \
        upk2(Zn01, z0, z1); upk2(Zn23, z2, z3);                                 \
        ull o01 = b01, o23 = b23, zb;                                           \
        zb = pk2(z0, z0); o01 = fma2_(zb, E0[0], o01); o23 = fma2_(zb, E1[0], o23); \
        zb = pk2(z1, z1); o01 = fma2_(zb, E0[1], o01); o23 = fma2_(zb, E1[1], o23); \
        zb = pk2(z2, z2); o01 = fma2_(zb, E0[2], o01); o23 = fma2_(zb, E1[2], o23); \
        zb = pk2(z3, z3); o01 = fma2_(zb, E0[3], o01); o23 = fma2_(zb, E1[3], o23); \
        upk2(o01, G0.C, G1.C); upk2(o23, G2.C, G3.C);                           \
    } while (0)

__global__ void __launch_bounds__(TPB, 4) lieflow_main(
    const float* __restrict__ data,
    const float* __restrict__ bs,
    const int*   __restrict__ idxs,
    float*       __restrict__ out,
    int write_logdet)
{
    float* buf0 = smem;                  // 4096 floats
    float* buf1 = smem + RPB * NF;       // 4096 floats
    float* redm = smem + 2 * RPB * NF;   // RPB * 8 floats

    const int tid = threadIdx.x;         // == feature block n (0..255)
    const int n   = tid;
    const int rowBase = blockIdx.x * RPB;

    const ull ONE2   = pk2(1.f, 1.f);
    const ull HALF2  = pk2(0.5f, 0.5f);
    const ull NHALF2 = pk2(-0.5f, -0.5f);

    float accp[RPB];
#pragma unroll
    for (int i = 0; i < RPB; i++) accp[i] = 1.f;

    // ---- layer 0: gmem rows -> matmul(E0)+b0 -> transposed store into buf0 ----
    {
        ull E0[4], E1[4];
#pragma unroll
        for (int e = 0; e < 4; e++) {
            E0[e] = g_Epk[((0 * 2 + 0) * 4 + e) * NB + n];
            E1[e] = g_Epk[((0 * 2 + 1) * 4 + e) * NB + n];
        }
        float4 bv = *(const float4*)(bs + 4 * n);
        ull b01 = pk2(bv.x, bv.y), b23 = pk2(bv.z, bv.w);

        float4 G0, G1, G2, G3;   // G{k}.{row} = output feature 4n+k, row rl
#pragma unroll
        for (int rl = 0; rl < RPB; rl++) {
            float4 z = *(const float4*)(data + (size_t)(rowBase + rl) * NF + 4 * n);
            ull o01 = b01, o23 = b23, zb;
            zb = pk2(z.x, z.x); o01 = fma2_(zb, E0[0], o01); o23 = fma2_(zb, E1[0], o23);
            zb = pk2(z.y, z.y); o01 = fma2_(zb, E0[1], o01); o23 = fma2_(zb, E1[1], o23);
            zb = pk2(z.z, z.z); o01 = fma2_(zb, E0[2], o01); o23 = fma2_(zb, E1[2], o23);
            zb = pk2(z.w, z.w); o01 = fma2_(zb, E0[3], o01); o23 = fma2_(zb, E1[3], o23);
            float ox, oy, oz, ow;
            upk2(o01, ox, oy); upk2(o23, oz, ow);
            if (rl == 0) { G0.x = ox; G1.x = oy; G2.x = oz; G3.x = ow; }
            if (rl == 1) { G0.y = ox; G1.y = oy; G2.y = oz; G3.y = ow; }
            if (rl == 2) { G0.z = ox; G1.z = oy; G2.z = oz; G3.z = ow; }
            if (rl == 3) { G0.w = ox; G1.w = oy; G2.w = oz; G3.w = ow; }
        }
        float4* d = (float4*)buf0;
        d[0 * 256 + n] = G0;   // feature 4n+0 chunk
        d[1 * 256 + n] = G1;   // feature 4n+1
        d[2 * 256 + n] = G2;   // feature 4n+2
        d[3 * 256 + n] = G3;   // feature 4n+3
    }
    __syncthreads();

    // ---- layers 1..16: LDS.128 gather -> bent -> matmul -> STS.128 store ----
#pragma unroll 1
    for (int l = 1; l < NL; l++) {
        float* src = (l & 1) ? buf0 : buf1;
        float* dst = (l & 1) ? buf1 : buf0;

        ull E0[4], E1[4];
#pragma unroll
        for (int e = 0; e < 4; e++) {
            E0[e] = g_Epk[((l * 2 + 0) * 4 + e) * NB + n];
            E1[e] = g_Epk[((l * 2 + 1) * 4 + e) * NB + n];
        }
        float4 bv = *(const float4*)(bs + l * NF + 4 * n);
        ull b01 = pk2(bv.x, bv.y), b23 = pk2(bv.z, bv.w);
        int4 gi = *(const int4*)(idxs + (l - 1) * NF + 4 * n);

        // gather: one LDS.128 per input feature, covering all 4 rows
        float4 G0 = *CHUNK(src, gi.x);
        float4 G1 = *CHUNK(src, gi.y);
        float4 G2 = *CHUNK(src, gi.z);
        float4 G3 = *CHUNK(src, gi.w);

        ROWBODY(x, 0);
        ROWBODY(y, 1);
        ROWBODY(z, 2);
        ROWBODY(w, 3);

        float4* d = (float4*)dst;
        d[0 * 256 + n] = G0;
        d[1 * 256 + n] = G1;
        d[2 * 256 + n] = G2;
        d[3 * 256 + n] = G3;
        __syncthreads();
    }

    // ---- final permutation (idx[16]) + coalesced global write (from buf0) ----
    {
        int4 gi = *(const int4*)(idxs + (NL - 1) * NF + 4 * n);
        float4 G0 = *CHUNK(buf0, gi.x);
        float4 G1 = *CHUNK(buf0, gi.y);
        float4 G2 = *CHUNK(buf0, gi.z);
        float4 G3 = *CHUNK(buf0, gi.w);
        float4* orow;
        orow = (float4*)(out + (size_t)(rowBase + 0) * NF + 4 * n);
        *orow = make_float4(G0.x, G1.x, G2.x, G3.x);
        orow = (float4*)(out + (size_t)(rowBase + 1) * NF + 4 * n);
        *orow = make_float4(G0.y, G1.y, G2.y, G3.y);
        orow = (float4*)(out + (size_t)(rowBase + 2) * NF + 4 * n);
        *orow = make_float4(G0.z, G1.z, G2.z, G3.z);
        orow = (float4*)(out + (size_t)(rowBase + 3) * NF + 4 * n);
        *orow = make_float4(G0.w, G1.w, G2.w, G3.w);
    }

    // ---- logdet reduction (one lg2 per row per thread) ----
    __syncthreads();
    const int wid = tid >> 5, lane = tid & 31;
#pragma unroll
    for (int rl = 0; rl < RPB; rl++) {
        float v = lg2_(accp[rl]);
#pragma unroll
        for (int o = 16; o > 0; o >>= 1) v += __shfl_xor_sync(0xffffffffu, v, o);
        if (lane == 0) redm[rl * 8 + wid] = v;
    }
    __syncthreads();
    if (write_logdet && tid < RPB) {
        float s = 0.f;
#pragma unroll
        for (int j = 0; j < 8; j++) s += redm[tid * 8 + j];
        out[(size_t)BATCHN * NF + rowBase + tid] =
            -0.6931471805599453f * s - g_trace[0];
    }
}

// ---------- launch ----------
extern "C" void kernel_launch(void* const* d_in, const int* in_sizes, int n_in,
                              void* d_out, int out_size) {
    const float* data = (const float*)d_in[0];
    const float* vs   = (const float*)d_in[1];
    const float* bsp  = (const float*)d_in[2];
    const int*   idxs = (const int*)d_in[3];
    float* out = (float*)d_out;

    const int smem_bytes = (2 * RPB * NF + RPB * 8) * 4;
    cudaFuncSetAttribute(lieflow_main, cudaFuncAttributeMaxDynamicSharedMemorySize, smem_bytes);

    prep_expm<<<(NL * NB + 255) / 256, 256>>>(vs);
    prep_trace<<<1, 256>>>(vs);

    int write_logdet = (out_size >= BATCHN * NF + BATCHN) ? 1 : 0;
    lieflow_main<<<BATCHN / RPB, TPB, smem_bytes>>>(data, bsp, idxs, out, write_logdet);
}

// round 11
// speedup vs baseline: 1.0124x; 1.0124x over previous
#include <cuda_runtime.h>
#include <cstdint>

#define NF      1024
#define NB      256
#define NL      17
#define BATCHN  16384
#define RPB     4           // rows per CTA (hardcoded in transposed layout)
#define TPB     256

typedef unsigned long long ull;

// ---------- packed f32x2 helpers ----------
__device__ __forceinline__ ull pk2(float lo, float hi) {
    ull r; asm("mov.b64 %0,{%1,%2};" : "=l"(r) : "f"(lo), "f"(hi)); return r;
}
__device__ __forceinline__ void upk2(ull v, float& a, float& b) {
    asm("mov.b64 {%0,%1},%2;" : "=f"(a), "=f"(b) : "l"(v));
}
__device__ __forceinline__ ull fma2_(ull a, ull b, ull c) {
    ull d; asm("fma.rn.f32x2 %0,%1,%2,%3;" : "=l"(d) : "l"(a), "l"(b), "l"(c)); return d;
}
__device__ __forceinline__ ull mul2_(ull a, ull b) {
    ull d; asm("mul.rn.f32x2 %0,%1,%2;" : "=l"(d) : "l"(a), "l"(b)); return d;
}
__device__ __forceinline__ ull add2_(ull a, ull b) {
    ull d; asm("add.rn.f32x2 %0,%1,%2;" : "=l"(d) : "l"(a), "l"(b)); return d;
}
__device__ __forceinline__ float rsq_(float x) {
    float r; asm("rsqrt.approx.f32 %0,%1;" : "=f"(r) : "f"(x)); return r;
}
__device__ __forceinline__ float lg2_(float x) {
    float r; asm("lg2.approx.f32 %0,%1;" : "=f"(r) : "f"(x)); return r;
}

// ---------- device scratch ----------
__device__ ull   g_Epk[NL * 2 * 4 * NB];
__device__ float g_traceL[NL];

// ---------- prep: expm of each 4x4 block + per-layer trace ----------
// grid = 17 blocks of 256: block b handles exactly layer b (NB == blockDim).
__global__ void prep_expm(const float* __restrict__ vs) {
    __shared__ float red[256];
    int m = blockIdx.x * blockDim.x + threadIdx.x;
    const float* src = vs + m * 16;
    float A[16];
#pragma unroll
    for (int i = 0; i < 16; i++) A[i] = src[i];

    // per-layer trace partial (deterministic fixed-tree reduction)
    red[threadIdx.x] = A[0] + A[5] + A[10] + A[15];
    __syncthreads();
    for (int o = 128; o > 0; o >>= 1) {
        if (threadIdx.x < o) red[threadIdx.x] += red[threadIdx.x + o];
        __syncthreads();
    }
    if (threadIdx.x == 0) g_traceL[blockIdx.x] = red[0];

    float nrm = 0.f;
#pragma unroll
    for (int r = 0; r < 4; r++) {
        float s = fabsf(A[r * 4 + 0]) + fabsf(A[r * 4 + 1]) +
                  fabsf(A[r * 4 + 2]) + fabsf(A[r * 4 + 3]);
        nrm = fmaxf(nrm, s);
    }
    int sc = 0;
    while (nrm > 0.25f && sc < 40) { nrm *= 0.5f; sc++; }
    float f = 1.f;
    for (int i = 0; i < sc; i++) f *= 0.5f;
#pragma unroll
    for (int i = 0; i < 16; i++) A[i] *= f;

    // order-9 Taylor
    float X[16], T[16];
#pragma unroll
    for (int i = 0; i < 16; i++) { X[i] = A[i]; T[i] = A[i]; }
    X[0] += 1.f; X[5] += 1.f; X[10] += 1.f; X[15] += 1.f;

#pragma unroll 1
    for (int k = 2; k <= 9; k++) {
        float Tn[16];
        float inv = 1.f / (float)k;
#pragma unroll
        for (int r = 0; r < 4; r++)
#pragma unroll
            for (int c = 0; c < 4; c++) {
                float s = T[r * 4 + 0] * A[0 * 4 + c];
                s = fmaf(T[r * 4 + 1], A[1 * 4 + c], s);
                s = fmaf(T[r * 4 + 2], A[2 * 4 + c], s);
                s = fmaf(T[r * 4 + 3], A[3 * 4 + c], s);
                Tn[r * 4 + c] = s * inv;
            }
#pragma unroll
        for (int i = 0; i < 16; i++) { T[i] = Tn[i]; X[i] += T[i]; }
    }
#pragma unroll 1
    for (int q = 0; q < sc; q++) {
        float Xn[16];
#pragma unroll
        for (int r = 0; r < 4; r++)
#pragma unroll
            for (int c = 0; c < 4; c++) {
                float s = X[r * 4 + 0] * X[0 * 4 + c];
                s = fmaf(X[r * 4 + 1], X[1 * 4 + c], s);
                s = fmaf(X[r * 4 + 2], X[2 * 4 + c], s);
                s = fmaf(X[r * 4 + 3], X[3 * 4 + c], s);
                Xn[r * 4 + c] = s;
            }
#pragma unroll
        for (int i = 0; i < 16; i++) X[i] = Xn[i];
    }

    int l = blockIdx.x, n = threadIdx.x;
    float2* Ep = (float2*)g_Epk;
#pragma unroll
    for (int e = 0; e < 4; e++) {
        Ep[((l * 2 + 0) * 4 + e) * NB + n] = make_float2(X[e * 4 + 0], X[e * 4 + 1]);
        Ep[((l * 2 + 1) * 4 + e) * NB + n] = make_float2(X[e * 4 + 2], X[e * 4 + 3]);
    }
}

// ---------- main fused flow kernel ----------
// Transposed+swizzled smem layout: element (feature f, row rl) at float offset
//   (f & 3) * 1024 + (f >> 2) * 4 + rl
// -> one float4 chunk per feature holds all RPB=4 rows.
extern __shared__ float smem[];

#define CHUNK(bufp, g) (((float4*)(bufp)) + (((g) & 3) << 8) + ((g) >> 2))

#define ROWBODY(C, RL)                                                          \
    do {                                                                        \
        ull Z01 = pk2(G0.C, G1.C), Z23 = pk2(G2.C, G3.C);                       \
        ull T01 = fma2_(Z01, Z01, ONE2), T23 = fma2_(Z23, Z23, ONE2);           \
        float t0, t1, t2, t3;                                                   \
        upk2(T01, t0, t1); upk2(T23, t2, t3);                                   \
        ull R01 = pk2(rsq_(t0), rsq_(t1)), R23 = pk2(rsq_(t2), rsq_(t3));       \
        ull S01 = mul2_(T01, R01), S23 = mul2_(T23, R23);                       \
        ull U01 = mul2_(Z01, R01), U23 = mul2_(Z23, R23);                       \
        ull D01 = fma2_(HALF2, U01, ONE2), D23 = fma2_(HALF2, U23, ONE2);       \
        ull P = mul2_(D01, D23);                                                \
        float p0, p1; upk2(P, p0, p1);                                          \
        accp[RL] *= (p0 * p1);                                                  \
        ull Zn01 = add2_(fma2_(HALF2, S01, Z01), NHALF2);                       \
        ull Zn23 = add2_(fma2_(HALF2, S23, Z23), NHALF2);                       \
        float z0, z1, z2, z3;                                                   \
        upk2(Zn01, z0, z1); upk2(Zn23, z2, z3);                                 \
        ull o01 = b01, o23 = b23, zb;                                           \
        zb = pk2(z0, z0); o01 = fma2_(zb, E0[0], o01); o23 = fma2_(zb, E1[0], o23); \
        zb = pk2(z1, z1); o01 = fma2_(zb, E0[1], o01); o23 = fma2_(zb, E1[1], o23); \
        zb = pk2(z2, z2); o01 = fma2_(zb, E0[2], o01); o23 = fma2_(zb, E1[2], o23); \
        zb = pk2(z3, z3); o01 = fma2_(zb, E0[3], o01); o23 = fma2_(zb, E1[3], o23); \
        upk2(o01, G0.C, G1.C); upk2(o23, G2.C, G3.C);                           \
    } while (0)

__global__ void __launch_bounds__(TPB, 4) lieflow_main(
    const float* __restrict__ data,
    const float* __restrict__ bs,
    const int*   __restrict__ idxs,
    float*       __restrict__ out,
    int write_logdet)
{
    float* buf0 = smem;                  // 4096 floats
    float* buf1 = smem + RPB * NF;       // 4096 floats
    float* redm = smem + 2 * RPB * NF;   // RPB * 8 floats

    const int tid = threadIdx.x;         // == feature block n (0..255)
    const int n   = tid;
    const int rowBase = blockIdx.x * RPB;

    const ull ONE2   = pk2(1.f, 1.f);
    const ull HALF2  = pk2(0.5f, 0.5f);
    const ull NHALF2 = pk2(-0.5f, -0.5f);

    float accp[RPB];
#pragma unroll
    for (int i = 0; i < RPB; i++) accp[i] = 1.f;

    // ---- layer 0: gmem rows -> matmul(E0)+b0 -> transposed store into buf0 ----
    {
        ull E0[4], E1[4];
#pragma unroll
        for (int e = 0; e < 4; e++) {
            E0[e] = g_Epk[((0 * 2 + 0) * 4 + e) * NB + n];
            E1[e] = g_Epk[((0 * 2 + 1) * 4 + e) * NB + n];
        }
        float4 bv = *(const float4*)(bs + 4 * n);
        ull b01 = pk2(bv.x, bv.y), b23 = pk2(bv.z, bv.w);

        float4 G0, G1, G2, G3;
#pragma unroll
        for (int rl = 0; rl < RPB; rl++) {
            float4 z = *(const float4*)(data + (size_t)(rowBase + rl) * NF + 4 * n);
            ull o01 = b01, o23 = b23, zb;
            zb = pk2(z.x, z.x); o01 = fma2_(zb, E0[0], o01); o23 = fma2_(zb, E1[0], o23);
            zb = pk2(z.y, z.y); o01 = fma2_(zb, E0[1], o01); o23 = fma2_(zb, E1[1], o23);
            zb = pk2(z.z, z.z); o01 = fma2_(zb, E0[2], o01); o23 = fma2_(zb, E1[2], o23);
            zb = pk2(z.w, z.w); o01 = fma2_(zb, E0[3], o01); o23 = fma2_(zb, E1[3], o23);
            float ox, oy, oz, ow;
            upk2(o01, ox, oy); upk2(o23, oz, ow);
            if (rl == 0) { G0.x = ox; G1.x = oy; G2.x = oz; G3.x = ow; }
            if (rl == 1) { G0.y = ox; G1.y = oy; G2.y = oz; G3.y = ow; }
            if (rl == 2) { G0.z = ox; G1.z = oy; G2.z = oz; G3.z = ow; }
            if (rl == 3) { G0.w = ox; G1.w = oy; G2.w = oz; G3.w = ow; }
        }
        float4* d = (float4*)buf0;
        d[0 * 256 + n] = G0;
        d[1 * 256 + n] = G1;
        d[2 * 256 + n] = G2;
        d[3 * 256 + n] = G3;
    }
    __syncthreads();

    // prefetched permutation indices for layer 1
    int4 gi = *(const int4*)(idxs + 0 * NF + 4 * n);

    // ---- layers 1..16: gather -> bent -> matmul -> store (gi pipelined) ----
#pragma unroll 1
    for (int l = 1; l < NL; l++) {
        float* src = (l & 1) ? buf0 : buf1;
        float* dst = (l & 1) ? buf1 : buf0;

        // params for this layer (latency hidden under bent chain)
        ull E0[4], E1[4];
#pragma unroll
        for (int e = 0; e < 4; e++) {
            E0[e] = g_Epk[((l * 2 + 0) * 4 + e) * NB + n];
            E1[e] = g_Epk[((l * 2 + 1) * 4 + e) * NB + n];
        }
        float4 bv = *(const float4*)(bs + l * NF + 4 * n);
        ull b01 = pk2(bv.x, bv.y), b23 = pk2(bv.z, bv.w);

        // gather: one LDS.128 per input feature, covering all 4 rows
        float4 G0 = *CHUNK(src, gi.x);
        float4 G1 = *CHUNK(src, gi.y);
        float4 G2 = *CHUNK(src, gi.z);
        float4 G3 = *CHUNK(src, gi.w);

        // prefetch next layer's gi (layer l+1 uses idxs[l]; after l=16 this
        // loads idxs[16] = the final output permutation)
        int4 gin = *(const int4*)(idxs + l * NF + 4 * n);

        ROWBODY(x, 0);
        ROWBODY(y, 1);
        ROWBODY(z, 2);
        ROWBODY(w, 3);

        float4* d = (float4*)dst;
        d[0 * 256 + n] = G0;
        d[1 * 256 + n] = G1;
        d[2 * 256 + n] = G2;
        d[3 * 256 + n] = G3;
        __syncthreads();
        gi = gin;
    }

    // ---- final permutation (gi == idxs[16]) + coalesced global write ----
    {
        float4 G0 = *CHUNK(buf0, gi.x);
        float4 G1 = *CHUNK(buf0, gi.y);
        float4 G2 = *CHUNK(buf0, gi.z);
        float4 G3 = *CHUNK(buf0, gi.w);
        float4* orow;
        orow = (float4*)(out + (size_t)(rowBase + 0) * NF + 4 * n);
        *orow = make_float4(G0.x, G1.x, G2.x, G3.x);
        orow = (float4*)(out + (size_t)(rowBase + 1) * NF + 4 * n);
        *orow = make_float4(G0.y, G1.y, G2.y, G3.y);
        orow = (float4*)(out + (size_t)(rowBase + 2) * NF + 4 * n);
        *orow = make_float4(G0.z, G1.z, G2.z, G3.z);
        orow = (float4*)(out + (size_t)(rowBase + 3) * NF + 4 * n);
        *orow = make_float4(G0.w, G1.w, G2.w, G3.w);
    }

    // ---- logdet reduction (one lg2 per row per thread) ----
    __syncthreads();
    const int wid = tid >> 5, lane = tid & 31;
#pragma unroll
    for (int rl = 0; rl < RPB; rl++) {
        float v = lg2_(accp[rl]);
#pragma unroll
        for (int o = 16; o > 0; o >>= 1) v += __shfl_xor_sync(0xffffffffu, v, o);
        if (lane == 0) redm[rl * 8 + wid] = v;
    }
    __syncthreads();
    if (write_logdet && tid < RPB) {
        float s = 0.f;
#pragma unroll
        for (int j = 0; j < 8; j++) s += redm[tid * 8 + j];
        float tr = 0.f;
#pragma unroll
        for (int j = 0; j < NL; j++) tr += g_traceL[j];
        out[(size_t)BATCHN * NF + rowBase + tid] =
            -0.6931471805599453f * s - tr;
    }
}

// ---------- launch ----------
extern "C" void kernel_launch(void* const* d_in, const int* in_sizes, int n_in,
                              void* d_out, int out_size) {
    const float* data = (const float*)d_in[0];
    const float* vs   = (const float*)d_in[1];
    const float* bsp  = (const float*)d_in[2];
    const int*   idxs = (const int*)d_in[3];
    float* out = (float*)d_out;

    const int smem_bytes = (2 * RPB * NF + RPB * 8) * 4;
    cudaFuncSetAttribute(lieflow_main, cudaFuncAttributeMaxDynamicSharedMemorySize, smem_bytes);

    prep_expm<<<NL, NB>>>(vs);

    int write_logdet = (out_size >= BATCHN * NF + BATCHN) ? 1 : 0;
    lieflow_main<<<BATCHN / RPB, TPB, smem_bytes>>>(data, bsp, idxs, out, write_logdet);
}

// round 14
// speedup vs baseline: 1.0795x; 1.0663x over previous
#include <cuda_runtime.h>
#include <cstdint>

#define NF      1024
#define NB      256
#define NL      17
#define BATCHN  16384
#define RPB     8           // rows per CTA (two 4-row groups)
#define TPB     256

typedef unsigned long long ull;

// ---------- packed f32x2 helpers ----------
__device__ __forceinline__ ull pk2(float lo, float hi) {
    ull r; asm("mov.b64 %0,{%1,%2};" : "=l"(r) : "f"(lo), "f"(hi)); return r;
}
__device__ __forceinline__ void upk2(ull v, float& a, float& b) {
    asm("mov.b64 {%0,%1},%2;" : "=f"(a), "=f"(b) : "l"(v));
}
__device__ __forceinline__ ull fma2_(ull a, ull b, ull c) {
    ull d; asm("fma.rn.f32x2 %0,%1,%2,%3;" : "=l"(d) : "l"(a), "l"(b), "l"(c)); return d;
}
__device__ __forceinline__ ull mul2_(ull a, ull b) {
    ull d; asm("mul.rn.f32x2 %0,%1,%2;" : "=l"(d) : "l"(a), "l"(b)); return d;
}
__device__ __forceinline__ ull add2_(ull a, ull b) {
    ull d; asm("add.rn.f32x2 %0,%1,%2;" : "=l"(d) : "l"(a), "l"(b)); return d;
}
__device__ __forceinline__ float rsq_(float x) {
    float r; asm("rsqrt.approx.f32 %0,%1;" : "=f"(r) : "f"(x)); return r;
}
__device__ __forceinline__ float lg2_(float x) {
    float r; asm("lg2.approx.f32 %0,%1;" : "=f"(r) : "f"(x)); return r;
}

// ---------- device scratch ----------
__device__ ull   g_Epk[NL * 2 * 4 * NB];
__device__ float g_traceL[NL];

// ---------- prep: expm of each 4x4 block + per-layer trace ----------
__global__ void prep_expm(const float* __restrict__ vs) {
    __shared__ float red[256];
    int m = blockIdx.x * blockDim.x + threadIdx.x;
    const float* src = vs + m * 16;
    float A[16];
#pragma unroll
    for (int i = 0; i < 16; i++) A[i] = src[i];

    red[threadIdx.x] = A[0] + A[5] + A[10] + A[15];
    __syncthreads();
    for (int o = 128; o > 0; o >>= 1) {
        if (threadIdx.x < o) red[threadIdx.x] += red[threadIdx.x + o];
        __syncthreads();
    }
    if (threadIdx.x == 0) g_traceL[blockIdx.x] = red[0];

    float nrm = 0.f;
#pragma unroll
    for (int r = 0; r < 4; r++) {
        float s = fabsf(A[r * 4 + 0]) + fabsf(A[r * 4 + 1]) +
                  fabsf(A[r * 4 + 2]) + fabsf(A[r * 4 + 3]);
        nrm = fmaxf(nrm, s);
    }
    int sc = 0;
    while (nrm > 0.25f && sc < 40) { nrm *= 0.5f; sc++; }
    float f = 1.f;
    for (int i = 0; i < sc; i++) f *= 0.5f;
#pragma unroll
    for (int i = 0; i < 16; i++) A[i] *= f;

    float X[16], T[16];
#pragma unroll
    for (int i = 0; i < 16; i++) { X[i] = A[i]; T[i] = A[i]; }
    X[0] += 1.f; X[5] += 1.f; X[10] += 1.f; X[15] += 1.f;

#pragma unroll 1
    for (int k = 2; k <= 9; k++) {
        float Tn[16];
        float inv = 1.f / (float)k;
#pragma unroll
        for (int r = 0; r < 4; r++)
#pragma unroll
            for (int c = 0; c < 4; c++) {
                float s = T[r * 4 + 0] * A[0 * 4 + c];
                s = fmaf(T[r * 4 + 1], A[1 * 4 + c], s);
                s = fmaf(T[r * 4 + 2], A[2 * 4 + c], s);
                s = fmaf(T[r * 4 + 3], A[3 * 4 + c], s);
                Tn[r * 4 + c] = s * inv;
            }
#pragma unroll
        for (int i = 0; i < 16; i++) { T[i] = Tn[i]; X[i] += T[i]; }
    }
#pragma unroll 1
    for (int q = 0; q < sc; q++) {
        float Xn[16];
#pragma unroll
        for (int r = 0; r < 4; r++)
#pragma unroll
            for (int c = 0; c < 4; c++) {
                float s = X[r * 4 + 0] * X[0 * 4 + c];
                s = fmaf(X[r * 4 + 1], X[1 * 4 + c], s);
                s = fmaf(X[r * 4 + 2], X[2 * 4 + c], s);
                s = fmaf(X[r * 4 + 3], X[3 * 4 + c], s);
                Xn[r * 4 + c] = s;
            }
#pragma unroll
        for (int i = 0; i < 16; i++) X[i] = Xn[i];
    }

    int l = blockIdx.x, n = threadIdx.x;
    float2* Ep = (float2*)g_Epk;
#pragma unroll
    for (int e = 0; e < 4; e++) {
        Ep[((l * 2 + 0) * 4 + e) * NB + n] = make_float2(X[e * 4 + 0], X[e * 4 + 1]);
        Ep[((l * 2 + 1) * 4 + e) * NB + n] = make_float2(X[e * 4 + 2], X[e * 4 + 3]);
    }
}

// ---------- main fused flow kernel ----------
// Two 4-row groups per buffer. Element (feature f, row rl):
//   float offset = (rl>>2)*4096 + (f&3)*1024 + (f>>2)*4 + (rl&3)
// Gather = 1 LDS.128 per feature per group; stores conflict-free.
extern __shared__ float smem[];

// float4 chunk for feature g, row-group h
#define CHUNKH(bufp, h, g) (((float4*)(bufp)) + ((h) << 10) + (((g) & 3) << 8) + ((g) >> 2))

#define ROWBODY(C, RL)                                                          \
    do {                                                                        \
        ull Z01 = pk2(G0.C, G1.C), Z23 = pk2(G2.C, G3.C);                       \
        ull T01 = fma2_(Z01, Z01, ONE2), T23 = fma2_(Z23, Z23, ONE2);           \
        float t0, t1, t2, t3;                                                   \
        upk2(T01, t0, t1); upk2(T23, t2, t3);                                   \
        ull R01 = pk2(rsq_(t0), rsq_(t1)), R23 = pk2(rsq_(t2), rsq_(t3));       \
        ull S01 = mul2_(T01, R01), S23 = mul2_(T23, R23);                       \
        ull U01 = mul2_(Z01, R01), U23 = mul2_(Z23, R23);                       \
        ull D01 = fma2_(HALF2, U01, ONE2), D23 = fma2_(HALF2, U23, ONE2);       \
        ull P = mul2_(D01, D23);                                                \
        float p0, p1; upk2(P, p0, p1);                                          \
        accp[RL] *= (p0 * p1);                                                  \
        ull Zn01 = add2_(fma2_(HALF2, S01, Z01), NHALF2);                       \
        ull Zn23 = add2_(fma2_(HALF2, S23, Z23), NHALF2);                       \
        float z0, z1, z2, z3;                                                   \
        upk2(Zn01, z0, z1); upk2(Zn23, z2, z3);                                 \
        ull o01 = b01, o23 = b23, zb;                                           \
        zb = pk2(z0, z0); o01 = fma2_(zb, E0[0], o01); o23 = fma2_(zb, E1[0], o23); \
        zb = pk2(z1, z1); o01 = fma2_(zb, E0[1], o01); o23 = fma2_(zb, E1[1], o23); \
        zb = pk2(z2, z2); o01 = fma2_(zb, E0[2], o01); o23 = fma2_(zb, E1[2], o23); \
        zb = pk2(z3, z3); o01 = fma2_(zb, E0[3], o01); o23 = fma2_(zb, E1[3], o23); \
        upk2(o01, G0.C, G1.C); upk2(o23, G2.C, G3.C);                           \
    } while (0)

__global__ void __launch_bounds__(TPB, 3) lieflow_main(
    const float* __restrict__ data,
    const float* __restrict__ bs,
    const int*   __restrict__ idxs,
    float*       __restrict__ out,
    int write_logdet)
{
    float* buf0 = smem;                  // 8192 floats
    float* buf1 = smem + RPB * NF;       // 8192 floats
    float* redm = smem + 2 * RPB * NF;   // RPB * 8 floats

    const int tid = threadIdx.x;         // == feature block n (0..255)
    const int n   = tid;
    const int rowBase = blockIdx.x * RPB;

    const ull ONE2   = pk2(1.f, 1.f);
    const ull HALF2  = pk2(0.5f, 0.5f);
    const ull NHALF2 = pk2(-0.5f, -0.5f);

    float accp[RPB];
#pragma unroll
    for (int i = 0; i < RPB; i++) accp[i] = 1.f;

    // ---- layer 0: gmem rows -> matmul(E0)+b0 -> transposed store into buf0 ----
    {
        ull E0[4], E1[4];
#pragma unroll
        for (int e = 0; e < 4; e++) {
            E0[e] = g_Epk[((0 * 2 + 0) * 4 + e) * NB + n];
            E1[e] = g_Epk[((0 * 2 + 1) * 4 + e) * NB + n];
        }
        float4 bv = *(const float4*)(bs + 4 * n);
        ull b01 = pk2(bv.x, bv.y), b23 = pk2(bv.z, bv.w);

#pragma unroll
        for (int h = 0; h < 2; h++) {
            float4 G0, G1, G2, G3;
#pragma unroll
            for (int rl = 0; rl < 4; rl++) {
                float4 z = *(const float4*)(data + (size_t)(rowBase + h * 4 + rl) * NF + 4 * n);
                ull o01 = b01, o23 = b23, zb;
                zb = pk2(z.x, z.x); o01 = fma2_(zb, E0[0], o01); o23 = fma2_(zb, E1[0], o23);
                zb = pk2(z.y, z.y); o01 = fma2_(zb, E0[1], o01); o23 = fma2_(zb, E1[1], o23);
                zb = pk2(z.z, z.z); o01 = fma2_(zb, E0[2], o01); o23 = fma2_(zb, E1[2], o23);
                zb = pk2(z.w, z.w); o01 = fma2_(zb, E0[3], o01); o23 = fma2_(zb, E1[3], o23);
                float ox, oy, oz, ow;
                upk2(o01, ox, oy); upk2(o23, oz, ow);
                if (rl == 0) { G0.x = ox; G1.x = oy; G2.x = oz; G3.x = ow; }
                if (rl == 1) { G0.y = ox; G1.y = oy; G2.y = oz; G3.y = ow; }
                if (rl == 2) { G0.z = ox; G1.z = oy; G2.z = oz; G3.z = ow; }
                if (rl == 3) { G0.w = ox; G1.w = oy; G2.w = oz; G3.w = ow; }
            }
            float4* d = (float4*)buf0 + (h << 10);
            d[0 * 256 + n] = G0;
            d[1 * 256 + n] = G1;
            d[2 * 256 + n] = G2;
            d[3 * 256 + n] = G3;
        }
    }
    __syncthreads();

    // prefetched permutation indices for layer 1
    int4 gi = *(const int4*)(idxs + 0 * NF + 4 * n);

    // ---- layers 1..16 ----
#pragma unroll 1
    for (int l = 1; l < NL; l++) {
        float* src = (l & 1) ? buf0 : buf1;
        float* dst = (l & 1) ? buf1 : buf0;

        ull E0[4], E1[4];
#pragma unroll
        for (int e = 0; e < 4; e++) {
            E0[e] = g_Epk[((l * 2 + 0) * 4 + e) * NB + n];
            E1[e] = g_Epk[((l * 2 + 1) * 4 + e) * NB + n];
        }
        float4 bv = *(const float4*)(bs + l * NF + 4 * n);
        ull b01 = pk2(bv.x, bv.y), b23 = pk2(bv.z, bv.w);

        int4 gin = *(const int4*)(idxs + l * NF + 4 * n);

        // row-group 0
        {
            float4 G0 = *CHUNKH(src, 0, gi.x);
            float4 G1 = *CHUNKH(src, 0, gi.y);
            float4 G2 = *CHUNKH(src, 0, gi.z);
            float4 G3 = *CHUNKH(src, 0, gi.w);
            ROWBODY(x, 0);
            ROWBODY(y, 1);
            ROWBODY(z, 2);
            ROWBODY(w, 3);
            float4* d = (float4*)dst;
            d[0 * 256 + n] = G0;
            d[1 * 256 + n] = G1;
            d[2 * 256 + n] = G2;
            d[3 * 256 + n] = G3;
        }
        // row-group 1
        {
            float4 G0 = *CHUNKH(src, 1, gi.x);
            float4 G1 = *CHUNKH(src, 1, gi.y);
            float4 G2 = *CHUNKH(src, 1, gi.z);
            float4 G3 = *CHUNKH(src, 1, gi.w);
            ROWBODY(x, 4);
            ROWBODY(y, 5);
            ROWBODY(z, 6);
            ROWBODY(w, 7);
            float4* d = (float4*)dst + (1 << 10);
            d[0 * 256 + n] = G0;
            d[1 * 256 + n] = G1;
            d[2 * 256 + n] = G2;
            d[3 * 256 + n] = G3;
        }
        __syncthreads();
        gi = gin;
    }

    // ---- final permutation (gi == idxs[16]) + coalesced global write ----
#pragma unroll
    for (int h = 0; h < 2; h++) {
        float4 G0 = *CHUNKH(buf0, h, gi.x);
        float4 G1 = *CHUNKH(buf0, h, gi.y);
        float4 G2 = *CHUNKH(buf0, h, gi.z);
        float4 G3 = *CHUNKH(buf0, h, gi.w);
        float4* orow;
        orow = (float4*)(out + (size_t)(rowBase + h * 4 + 0) * NF + 4 * n);
        *orow = make_float4(G0.x, G1.x, G2.x, G3.x);
        orow = (float4*)(out + (size_t)(rowBase + h * 4 + 1) * NF + 4 * n);
        *orow = make_float4(G0.y, G1.y, G2.y, G3.y);
        orow = (float4*)(out + (size_t)(rowBase + h * 4 + 2) * NF + 4 * n);
        *orow = make_float4(G0.z, G1.z, G2.z, G3.z);
        orow = (float4*)(out + (size_t)(rowBase + h * 4 + 3) * NF + 4 * n);
        *orow = make_float4(G0.w, G1.w, G2.w, G3.w);
    }

    // ---- logdet reduction (one lg2 per row per thread) ----
    __syncthreads();
    const int wid = tid >> 5, lane = tid & 31;
#pragma unroll
    for (int rl = 0; rl < RPB; rl++) {
        float v = lg2_(accp[rl]);
#pragma unroll
        for (int o = 16; o > 0; o >>= 1) v += __shfl_xor_sync(0xffffffffu, v, o);
        if (lane == 0) redm[rl * 8 + wid] = v;
    }
    __syncthreads();
    if (write_logdet && tid < RPB) {
        float s = 0.f;
#pragma unroll
        for (int j = 0; j < 8; j++) s += redm[tid * 8 + j];
        float tr = 0.f;
#pragma unroll
        for (int j = 0; j < NL; j++) tr += g_traceL[j];
        out[(size_t)BATCHN * NF + rowBase + tid] =
            -0.6931471805599453f * s - tr;
    }
}

// ---------- launch ----------
extern "C" void kernel_launch(void* const* d_in, const int* in_sizes, int n_in,
                              void* d_out, int out_size) {
    const float* data = (const float*)d_in[0];
    const float* vs   = (const float*)d_in[1];
    const float* bsp  = (const float*)d_in[2];
    const int*   idxs = (const int*)d_in[3];
    float* out = (float*)d_out;

    const int smem_bytes = (2 * RPB * NF + RPB * 8) * 4;
    cudaFuncSetAttribute(lieflow_main, cudaFuncAttributeMaxDynamicSharedMemorySize, smem_bytes);

    prep_expm<<<NL, NB>>>(vs);

    int write_logdet = (out_size >= BATCHN * NF + BATCHN) ? 1 : 0;
    lieflow_main<<<BATCHN / RPB, TPB, smem_bytes>>>(data, bsp, idxs, out, write_logdet);
}